// round 9
// baseline (speedup 1.0000x reference)
#include <cuda_runtime.h>
#include <math.h>
#include <stdint.h>

#define B_    16
#define N_    785
#define C_    768
#define H_    12
#define HD_   64
#define M_    (B_*N_)        // 12560
#define QKVC  (3*C_)         // 2304
#define LEFT  549
#define NM1   784
#define SCALE_ 0.125f

// output segment offsets (floats): [out | idx | index | cls_attn]
#define OFF_OUT   0
#define OFF_IDX   9646080
#define OFF_INDEX 9654864
#define OFF_CLS   16400976

// scratch (static device allocations; no runtime malloc)
__device__ float g_qkv[M_ * QKVC];                  // [B*N, 3C]
__device__ float g_attn[(size_t)B_ * H_ * N_ * N_]; // [B*H, N, N]
__device__ float g_attnout[M_ * C_];                // [B*N, C] head-interleaved
__device__ float g_q0[B_ * C_];                     // exact q row 0 per batch
__device__ float g_clsS[B_ * H_ * N_];              // exact row-0 scores
__device__ float g_ph[B_ * H_ * N_];                // cls-row softmax per head
__device__ float g_cls[B_ * NM1];
__device__ int   g_idx[B_ * LEFT];

// ---------------------------------------------------------------------------
// Cephes-style expf (bit-matches reference exp). DO NOT TOUCH — cls path.
// ---------------------------------------------------------------------------
__device__ __forceinline__ float cephes_expf(float x)
{
    x = fminf(x, 88.723164f);
    x = fmaxf(x, -87.33654f);
    float m = floorf(fmaf(x, 1.44269504088896341f, 0.5f));
    float r = fmaf(m, -0.693359375f, x);
    r = fmaf(m, 2.12194440e-4f, r);
    float r2 = r * r;
    float y = 1.9875691500E-4f;
    y = fmaf(y, r, 1.3981999507E-3f);
    y = fmaf(y, r, 8.3334519073E-3f);
    y = fmaf(y, r, 4.1665795894E-2f);
    y = fmaf(y, r, 1.6666665459E-1f);
    y = fmaf(y, r, 5.0000001201E-1f);
    y = fmaf(y, r2, r);
    y = y + 1.0f;
    int mi = (int)m;
    float s = __int_as_float((mi + 127) << 23);
    return y * s;
}

// ---------------------------------------------------------------------------
// tf32 helpers
// ---------------------------------------------------------------------------
__device__ __forceinline__ uint32_t f2tf(float f)
{
    uint32_t r;
    asm("cvt.rna.tf32.f32 %0, %1;" : "=r"(r) : "f"(f));
    return r;
}

__device__ __forceinline__ void mma8(float* c, const uint32_t* a, const uint32_t* b)
{
    asm volatile(
        "mma.sync.aligned.m16n8k8.row.col.f32.tf32.tf32.f32 "
        "{%0,%1,%2,%3}, {%4,%5,%6,%7}, {%8,%9}, {%0,%1,%2,%3};"
        : "+f"(c[0]), "+f"(c[1]), "+f"(c[2]), "+f"(c[3])
        : "r"(a[0]), "r"(a[1]), "r"(a[2]), "r"(a[3]), "r"(b[0]), "r"(b[1]));
}

// ---------------------------------------------------------------------------
// Generic batched TF32x3 GEMM: C = scale * A·B^T (+bias), fp32-grade accuracy.
// A row-major [M][K] (lda). BNT=true: Bg is [n][k] (lda=ldb, NT GEMM).
// BNT=false: Bg is [k][n] (NN GEMM). 256 threads; warp grid 2(m)x4(n).
// Batch pointers: base + (z/H)*Xb + (z%H)*Xh.
// ---------------------------------------------------------------------------
template<int BM, int BN, bool BNT>
__global__ __launch_bounds__(256) void mma_gemm(
    const float* __restrict__ Ag, int lda, long long Ab, long long Ah,
    const float* __restrict__ Bg, int ldb, long long Bb, long long Bh,
    float* __restrict__ Cg, int ldc, long long Cb, long long Ch,
    const float* __restrict__ bias, int M, int Nn, int K, float scale)
{
    constexpr int SA  = 20;         // As row stride (16 + 4 pad): conflict-free frag loads
    constexpr int SB  = BN + 8;     // Bs row stride: conflict-free frag loads
    constexpr int WTM = BM / 2, WTN = BN / 4;
    constexpr int MT  = WTM / 16, NT = WTN / 8;
    constexpr int NAL = (BM * 16) / (4 * 256);   // float4-groups per thread (A)
    constexpr int NBL = (BN * 16) / (4 * 256);   // (B)

    __shared__ uint32_t AsH[BM * SA], AsL[BM * SA];
    __shared__ uint32_t BsH[16 * SB], BsL[16 * SB];

    int z  = blockIdx.z;
    int zb = z / H_, zh = z - zb * H_;
    const float* A  = Ag + zb * Ab + zh * Ah;
    const float* Bp = Bg + zb * Bb + zh * Bh;
    float*       C  = Cg + zb * Cb + zh * Ch;

    int t = threadIdx.x, lane = t & 31, warp = t >> 5;
    int wm = warp & 1, wn = warp >> 1;
    int m0 = blockIdx.y * BM, n0 = blockIdx.x * BN;

    float acc[MT][NT][4];
#pragma unroll
    for (int mt = 0; mt < MT; mt++)
#pragma unroll
        for (int nt = 0; nt < NT; nt++)
#pragma unroll
            for (int i = 0; i < 4; i++) acc[mt][nt][i] = 0.f;

    for (int k0 = 0; k0 < K; k0 += 16) {
        // ---- A tile: [BM][16]
#pragma unroll
        for (int i = 0; i < NAL; i++) {
            int f = t + i * 256;
            int row = f >> 2;
            int kq = (f & 3) * 4;
            bool rok = (m0 + row < M);
#pragma unroll
            for (int j = 0; j < 4; j++) {
                int kk = k0 + kq + j;
                float v = (rok && kk < K) ? A[(size_t)(m0 + row) * lda + kk] : 0.f;
                uint32_t hi = f2tf(v);
                AsH[row * SA + kq + j] = hi;
                AsL[row * SA + kq + j] = f2tf(v - __uint_as_float(hi));
            }
        }
        // ---- B tile -> Bs[k][n]
        if (BNT) {
#pragma unroll
            for (int i = 0; i < NBL; i++) {
                int f = t + i * 256;
                int n = f >> 2;
                int kq = (f & 3) * 4;
                bool nok = (n0 + n < Nn);
#pragma unroll
                for (int j = 0; j < 4; j++) {
                    int kk = k0 + kq + j;
                    float v = (nok && kk < K) ? Bp[(size_t)(n0 + n) * ldb + kk] : 0.f;
                    uint32_t hi = f2tf(v);
                    BsH[(kq + j) * SB + n] = hi;
                    BsL[(kq + j) * SB + n] = f2tf(v - __uint_as_float(hi));
                }
            }
        } else {
#pragma unroll
            for (int i = 0; i < NBL; i++) {
                int f = t + i * 256;
                int kr = f / (BN / 4);
                int n4 = (f % (BN / 4)) * 4;
                bool kok = (k0 + kr < K);
#pragma unroll
                for (int j = 0; j < 4; j++) {
                    int n = n4 + j;
                    float v = (kok && n0 + n < Nn) ? Bp[(size_t)(k0 + kr) * ldb + n0 + n] : 0.f;
                    uint32_t hi = f2tf(v);
                    BsH[kr * SB + n] = hi;
                    BsL[kr * SB + n] = f2tf(v - __uint_as_float(hi));
                }
            }
        }
        __syncthreads();

#pragma unroll
        for (int k8 = 0; k8 < 16; k8 += 8) {
            uint32_t aH[MT][4], aL[MT][4], bH[NT][2], bL[NT][2];
#pragma unroll
            for (int mt = 0; mt < MT; mt++) {
                int r = wm * WTM + mt * 16 + (lane >> 2);
                int kq = k8 + (lane & 3);
                aH[mt][0] = AsH[r * SA + kq];       aH[mt][1] = AsH[(r + 8) * SA + kq];
                aH[mt][2] = AsH[r * SA + kq + 4];   aH[mt][3] = AsH[(r + 8) * SA + kq + 4];
                aL[mt][0] = AsL[r * SA + kq];       aL[mt][1] = AsL[(r + 8) * SA + kq];
                aL[mt][2] = AsL[r * SA + kq + 4];   aL[mt][3] = AsL[(r + 8) * SA + kq + 4];
            }
#pragma unroll
            for (int nt = 0; nt < NT; nt++) {
                int cN = wn * WTN + nt * 8 + (lane >> 2);
                int kr = k8 + (lane & 3);
                bH[nt][0] = BsH[kr * SB + cN];      bH[nt][1] = BsH[(kr + 4) * SB + cN];
                bL[nt][0] = BsL[kr * SB + cN];      bL[nt][1] = BsL[(kr + 4) * SB + cN];
            }
#pragma unroll
            for (int mt = 0; mt < MT; mt++)
#pragma unroll
                for (int nt = 0; nt < NT; nt++) {
                    mma8(acc[mt][nt], aL[mt], bH[nt]);
                    mma8(acc[mt][nt], aH[mt], bL[nt]);
                    mma8(acc[mt][nt], aH[mt], bH[nt]);
                }
        }
        __syncthreads();
    }

    // ---- epilogue
#pragma unroll
    for (int mt = 0; mt < MT; mt++) {
        int r0 = m0 + wm * WTM + mt * 16 + (lane >> 2);
#pragma unroll
        for (int nt = 0; nt < NT; nt++) {
            int cN = n0 + wn * WTN + nt * 8 + 2 * (lane & 3);
            float b0 = (bias && cN < Nn)     ? bias[cN]     : 0.f;
            float b1 = (bias && cN + 1 < Nn) ? bias[cN + 1] : 0.f;
            if (r0 < M) {
                if (cN < Nn)     C[(size_t)r0 * ldc + cN]     = acc[mt][nt][0] * scale + b0;
                if (cN + 1 < Nn) C[(size_t)r0 * ldc + cN + 1] = acc[mt][nt][1] * scale + b1;
            }
            if (r0 + 8 < M) {
                if (cN < Nn)     C[(size_t)(r0 + 8) * ldc + cN]     = acc[mt][nt][2] * scale + b0;
                if (cN + 1 < Nn) C[(size_t)(r0 + 8) * ldc + cN + 1] = acc[mt][nt][3] * scale + b1;
            }
        }
    }
}

// ---------------------------------------------------------------------------
// EXACT SGEMM NT (cls path): C[m,n] = sum_k A[m,k]*Bw[n,k]; ascending-k chain.
// Used only for the K-projection now. Bit-frozen vs round 7.
// ---------------------------------------------------------------------------
__global__ __launch_bounds__(256) void sgemm128_nt(
    const float* __restrict__ A, const float* __restrict__ Bw,
    float* __restrict__ Cm, int M, int Nc, int K, int ldc)
{
    __shared__ float As[8][128];
    __shared__ float Bs[8][128];
    int t = threadIdx.x;
    int m0 = blockIdx.y * 128;
    int n0 = blockIdx.x * 128;

    int aRow = t >> 1;
    int aK   = (t & 1) * 4;

    int ty = t >> 4, tx = t & 15;
    int rowBase = ty * 8, colBase = tx * 8;

    float acc[8][8];
#pragma unroll
    for (int i = 0; i < 8; i++)
#pragma unroll
        for (int j = 0; j < 8; j++) acc[i][j] = 0.f;

    const float* aPtr = A + (size_t)(m0 + aRow) * K + aK;
    const float* bPtr = Bw + (size_t)(n0 + aRow) * K + aK;
    bool aOk = (m0 + aRow) < M;
    bool bOk = (n0 + aRow) < Nc;

    for (int k0 = 0; k0 < K; k0 += 8) {
        float4 av = aOk ? *(const float4*)(aPtr + k0)
                        : make_float4(0.f, 0.f, 0.f, 0.f);
        float4 bv = bOk ? *(const float4*)(bPtr + k0)
                        : make_float4(0.f, 0.f, 0.f, 0.f);
        As[aK + 0][aRow] = av.x; As[aK + 1][aRow] = av.y;
        As[aK + 2][aRow] = av.z; As[aK + 3][aRow] = av.w;
        Bs[aK + 0][aRow] = bv.x; Bs[aK + 1][aRow] = bv.y;
        Bs[aK + 2][aRow] = bv.z; Bs[aK + 3][aRow] = bv.w;
        __syncthreads();

#pragma unroll
        for (int k = 0; k < 8; k++) {
            float a[8], b[8];
            *(float4*)(a)     = *(float4*)&As[k][rowBase];
            *(float4*)(a + 4) = *(float4*)&As[k][rowBase + 4];
            *(float4*)(b)     = *(float4*)&Bs[k][colBase];
            *(float4*)(b + 4) = *(float4*)&Bs[k][colBase + 4];
#pragma unroll
            for (int i = 0; i < 8; i++)
#pragma unroll
                for (int j = 0; j < 8; j++)
                    acc[i][j] += a[i] * b[j];
        }
        __syncthreads();
    }

#pragma unroll
    for (int i = 0; i < 8; i++) {
        int m = m0 + rowBase + i;
        if (m >= M) continue;
        float* cp = Cm + (size_t)m * ldc + n0 + colBase;
        float4 c0, c1;
        c0.x = acc[i][0]; c0.y = acc[i][1]; c0.z = acc[i][2]; c0.w = acc[i][3];
        c1.x = acc[i][4]; c1.y = acc[i][5]; c1.z = acc[i][6]; c1.w = acc[i][7];
        *(float4*)(cp)     = c0;
        *(float4*)(cp + 4) = c1;
    }
}

// ---------------------------------------------------------------------------
// EXACT q row 0 per batch (ascending-k fma chain, bit-matches sgemm output).
// ---------------------------------------------------------------------------
__global__ void q0_exact(const float* __restrict__ x, const float* __restrict__ Wqkv)
{
    int b = blockIdx.x;
    const float* xr = x + (size_t)b * N_ * C_;   // CLS row of batch b
    for (int c = threadIdx.x; c < C_; c += blockDim.x) {
        const float* w = Wqkv + (size_t)c * C_;
        float acc = 0.f;
        for (int k = 0; k < C_; k++) acc = fmaf(xr[k], w[k], acc);
        g_q0[b * C_ + c] = acc;
    }
}

// ---------------------------------------------------------------------------
// EXACT row-0 scores: s[b,h,j] = 0.125 * sum_d q0_d * k_jd  (ascending d).
// Bit-matches round-7 attn_scores row 0.
// ---------------------------------------------------------------------------
__global__ void cls_scores()
{
    int z = blockIdx.x;
    int b = z / H_, h = z - b * H_;
    __shared__ float q0s[HD_];
    if (threadIdx.x < HD_) q0s[threadIdx.x] = g_q0[b * C_ + h * HD_ + threadIdx.x];
    __syncthreads();
    for (int j = threadIdx.x; j < N_; j += blockDim.x) {
        const float* kr = g_qkv + (size_t)(b * N_ + j) * QKVC + C_ + h * HD_;
        float acc = 0.f;
#pragma unroll
        for (int d = 0; d < HD_; d++) acc = fmaf(q0s[d], kr[d], acc);
        g_clsS[z * N_ + j] = acc * SCALE_;
    }
}

// ---------------------------------------------------------------------------
// REF-MATCHED cls-row softmax (bit-frozen vs round 7; source = g_clsS).
// ---------------------------------------------------------------------------
__global__ __launch_bounds__(256) void cls_row_ref()
{
    int z = blockIdx.x;
    const float* __restrict__ S = g_clsS + (size_t)z * N_;
    float* __restrict__ P = g_ph + (size_t)z * N_;

    int t = threadIdx.x;
    int lane = t & 31, wid = t >> 5;
    __shared__ float red[8];
    __shared__ float se[N_];
    __shared__ float zsh;

    float s[4];
    float mx = -INFINITY;
#pragma unroll
    for (int i = 0; i < 4; i++) {
        int j = t + i * 256;
        s[i] = (j < N_) ? S[j] : -INFINITY;
        mx = fmaxf(mx, s[i]);
    }
#pragma unroll
    for (int w = 16; w > 0; w >>= 1)
        mx = fmaxf(mx, __shfl_xor_sync(0xffffffffu, mx, w));
    if (lane == 0) red[wid] = mx;
    __syncthreads();
    mx = red[0];
#pragma unroll
    for (int w = 1; w < 8; w++) mx = fmaxf(mx, red[w]);

#pragma unroll
    for (int i = 0; i < 4; i++) {
        int j = t + i * 256;
        if (j < N_) se[j] = cephes_expf(s[i] - mx);
    }
    __syncthreads();

    if (t == 0) {
        float Z = 0.f;
        for (int j = 0; j < N_; j++) Z += se[j];   // canonical ascending order
        zsh = Z;
    }
    __syncthreads();
    float Z = zsh;

#pragma unroll
    for (int i = 0; i < 4; i++) {
        int j = t + i * 256;
        if (j < N_) P[j] = se[j] / Z;   // IEEE division
    }
}

// ---------------------------------------------------------------------------
// Row softmax over 785 elems (in place); fast path, feeds PV/out only.
// ---------------------------------------------------------------------------
__global__ __launch_bounds__(256) void softmax_rows()
{
    float* __restrict__ p = g_attn + (size_t)blockIdx.x * N_;
    int t = threadIdx.x;
    int lane = t & 31, wid = t >> 5;
    __shared__ float red[8];

    float v[4];
    float mx = -INFINITY;
#pragma unroll
    for (int i = 0; i < 4; i++) {
        int j = t + i * 256;
        v[i] = (j < N_) ? p[j] : -INFINITY;
        mx = fmaxf(mx, v[i]);
    }
#pragma unroll
    for (int s = 16; s > 0; s >>= 1)
        mx = fmaxf(mx, __shfl_xor_sync(0xffffffffu, mx, s));
    if (lane == 0) red[wid] = mx;
    __syncthreads();
    mx = red[0];
#pragma unroll
    for (int w = 1; w < 8; w++) mx = fmaxf(mx, red[w]);

    float sum = 0.f;
#pragma unroll
    for (int i = 0; i < 4; i++) {
        int j = t + i * 256;
        if (j < N_) { v[i] = __expf(v[i] - mx); sum += v[i]; }
    }
#pragma unroll
    for (int s = 16; s > 0; s >>= 1)
        sum += __shfl_xor_sync(0xffffffffu, sum, s);
    __syncthreads();
    if (lane == 0) red[wid] = sum;
    __syncthreads();
    sum = 0.f;
#pragma unroll
    for (int w = 0; w < 8; w++) sum += red[w];

    float inv = 1.f / sum;
#pragma unroll
    for (int i = 0; i < 4; i++) {
        int j = t + i * 256;
        if (j < N_) p[j] = v[i] * inv;
    }
}

// ---------------------------------------------------------------------------
// cls_attn mean over heads (bit-frozen vs round 7)
// ---------------------------------------------------------------------------
__global__ void cls_mean(float* __restrict__ out_f)
{
    int b = blockIdx.x;
    for (int j = 1 + threadIdx.x; j < N_; j += blockDim.x) {
        float s = 0.f;
#pragma unroll
        for (int h = 0; h < H_; h++)
            s += g_ph[(size_t)(b * H_ + h) * N_ + j];
        float v = s / 12.0f;
        g_cls[b * NM1 + (j - 1)] = v;
        out_f[OFF_CLS + b * NM1 + (j - 1)] = v;
    }
}

// ---------------------------------------------------------------------------
// top-549 by rank counting (ties -> lower index)
// ---------------------------------------------------------------------------
__global__ void topk_sel(float* __restrict__ out_f)
{
    int b = blockIdx.x;
    __shared__ float sv[NM1];
    for (int j = threadIdx.x; j < NM1; j += blockDim.x)
        sv[j] = g_cls[b * NM1 + j];
    __syncthreads();
    for (int j = threadIdx.x; j < NM1; j += blockDim.x) {
        float v = sv[j];
        int rank = 0;
        for (int i = 0; i < NM1; i++) {
            float w = sv[i];
            rank += (w > v) || (w == v && i < j);
        }
        if (rank < LEFT) {
            g_idx[b * LEFT + rank] = j;
            out_f[OFF_IDX + b * LEFT + rank] = (float)j;
        }
    }
}

__global__ void bcast_index(float* __restrict__ out_f)
{
    int total = B_ * LEFT * C_;
    for (int i = blockIdx.x * blockDim.x + threadIdx.x; i < total;
         i += gridDim.x * blockDim.x) {
        int b = i / (LEFT * C_);
        int r = (i / C_) % LEFT;
        out_f[OFF_INDEX + i] = (float)g_idx[b * LEFT + r];
    }
}

// ---------------------------------------------------------------------------
extern "C" void kernel_launch(void* const* d_in, const int* in_sizes, int n_in,
                              void* d_out, int out_size)
{
    const float* x     = (const float*)d_in[0];
    const float* Wqkv  = (const float*)d_in[1];
    const float* Wproj = (const float*)d_in[2];
    const float* bproj = (const float*)d_in[3];
    float* out_f = (float*)d_out;

    float *p_qkv, *p_attn, *p_attnout;
    cudaGetSymbolAddress((void**)&p_qkv, g_qkv);
    cudaGetSymbolAddress((void**)&p_attn, g_attn);
    cudaGetSymbolAddress((void**)&p_attnout, g_attnout);

    // 1. EXACT K-projection (cls path): k-columns of qkv, bit-frozen chain
    sgemm128_nt<<<dim3(6, 99), 256>>>(
        x, Wqkv + 768 * 768, p_qkv + 768, M_, 768, 768, QKVC);

    // 2. TF32x3 Q-projection
    mma_gemm<128, 128, true><<<dim3(6, 99, 1), 256>>>(
        x, C_, 0, 0, Wqkv, C_, 0, 0, p_qkv, QKVC, 0, 0,
        nullptr, M_, C_, C_, 1.f);

    // 3. TF32x3 V-projection
    mma_gemm<128, 128, true><<<dim3(6, 99, 1), 256>>>(
        x, C_, 0, 0, Wqkv + 1536 * 768, C_, 0, 0, p_qkv + 1536, QKVC, 0, 0,
        nullptr, M_, C_, C_, 1.f);

    // 4. EXACT q row 0 + row-0 scores (cls path)
    q0_exact<<<B_, 256>>>(x, Wqkv);
    cls_scores<<<B_ * H_, 256>>>();

    // 5. TF32x3 scores: S = 0.125 * Q K^T  (batched over b,h)
    mma_gemm<128, 128, true><<<dim3(7, 7, B_ * H_), 256>>>(
        p_qkv, QKVC, (long long)N_ * QKVC, HD_,
        p_qkv + C_, QKVC, (long long)N_ * QKVC, HD_,
        p_attn, N_, (long long)H_ * N_ * N_, (long long)N_ * N_,
        nullptr, N_, N_, HD_, SCALE_);

    // 6. cls softmax (bit-frozen) — reads g_clsS
    cls_row_ref<<<B_ * H_, 256>>>();

    // 7. softmax rows (feeds PV)
    softmax_rows<<<B_ * H_ * N_, 256>>>();

    // 8. TF32x3 PV: O = P V  (NN GEMM, batched)
    mma_gemm<128, 64, false><<<dim3(1, 7, B_ * H_), 256>>>(
        p_attn, N_, (long long)H_ * N_ * N_, (long long)N_ * N_,
        p_qkv + 2 * C_, QKVC, (long long)N_ * QKVC, HD_,
        p_attnout, C_, (long long)N_ * C_, HD_,
        nullptr, N_, HD_, N_, 1.f);

    // 9. TF32x3 out-projection + bias
    mma_gemm<128, 128, true><<<dim3(6, 99, 1), 256>>>(
        p_attnout, C_, 0, 0, Wproj, C_, 0, 0, out_f + OFF_OUT, C_, 0, 0,
        bproj, M_, C_, C_, 1.f);

    // 10. cls mean / topk / index broadcast (bit-frozen)
    cls_mean<<<B_, 256>>>(out_f);
    topk_sel<<<B_, 256>>>(out_f);
    bcast_index<<<512, 256>>>(out_f);
}

// round 14
// speedup vs baseline: 1.5747x; 1.5747x over previous
#include <cuda_runtime.h>
#include <cuda_bf16.h>
#include <math.h>
#include <stdint.h>

#define B_    16
#define N_    785
#define C_    768
#define H_    12
#define HD_   64
#define M_    (B_*N_)        // 12560
#define QKVC  (3*C_)         // 2304
#define LEFT  549
#define NM1   784
#define SCALE_ 0.125f

// output segment offsets (floats): [out | idx | index | cls_attn]
#define OFF_OUT   0
#define OFF_IDX   9646080
#define OFF_INDEX 9654864
#define OFF_CLS   16400976

// scratch (static device allocations; no runtime malloc)
__device__ float g_qkv[M_ * QKVC];                  // [B*N, 3C]
__device__ float g_attn[(size_t)B_ * H_ * N_ * N_]; // [B*H, N, N]
__device__ float g_attnout[M_ * C_];                // [B*N, C] head-interleaved
__device__ float g_q0[B_ * C_];                     // exact q row 0 per batch
__device__ float g_clsS[B_ * H_ * N_];              // exact row-0 scores
__device__ float g_ph[B_ * H_ * N_];                // cls-row softmax per head
__device__ float g_cls[B_ * NM1];
__device__ int   g_idx[B_ * LEFT];

// ---------------------------------------------------------------------------
// Cephes-style expf (bit-matches reference exp). DO NOT TOUCH — cls path.
// ---------------------------------------------------------------------------
__device__ __forceinline__ float cephes_expf(float x)
{
    x = fminf(x, 88.723164f);
    x = fmaxf(x, -87.33654f);
    float m = floorf(fmaf(x, 1.44269504088896341f, 0.5f));
    float r = fmaf(m, -0.693359375f, x);
    r = fmaf(m, 2.12194440e-4f, r);
    float r2 = r * r;
    float y = 1.9875691500E-4f;
    y = fmaf(y, r, 1.3981999507E-3f);
    y = fmaf(y, r, 8.3334519073E-3f);
    y = fmaf(y, r, 4.1665795894E-2f);
    y = fmaf(y, r, 1.6666665459E-1f);
    y = fmaf(y, r, 5.0000001201E-1f);
    y = fmaf(y, r2, r);
    y = y + 1.0f;
    int mi = (int)m;
    float s = __int_as_float((mi + 127) << 23);
    return y * s;
}

// ---------------------------------------------------------------------------
// bf16 split helpers: pack two consecutive-k values into hi/lo bf16x2 words.
// value = hi + lo + O(2^-18 rel)
// ---------------------------------------------------------------------------
__device__ __forceinline__ void bsplit2(float a, float b, uint32_t& hi, uint32_t& lo)
{
    __nv_bfloat16 ah = __float2bfloat16_rn(a);
    __nv_bfloat16 bh = __float2bfloat16_rn(b);
    float ar = a - __bfloat162float(ah);
    float br = b - __bfloat162float(bh);
    __nv_bfloat16 al = __float2bfloat16_rn(ar);
    __nv_bfloat16 bl = __float2bfloat16_rn(br);
    hi = ((uint32_t)__bfloat16_as_ushort(bh) << 16) | (uint32_t)__bfloat16_as_ushort(ah);
    lo = ((uint32_t)__bfloat16_as_ushort(bl) << 16) | (uint32_t)__bfloat16_as_ushort(al);
}

__device__ __forceinline__ void mma16(float* c, const uint32_t* a, const uint32_t* b)
{
    asm volatile(
        "mma.sync.aligned.m16n8k16.row.col.f32.bf16.bf16.f32 "
        "{%0,%1,%2,%3}, {%4,%5,%6,%7}, {%8,%9}, {%0,%1,%2,%3};"
        : "+f"(c[0]), "+f"(c[1]), "+f"(c[2]), "+f"(c[3])
        : "r"(a[0]), "r"(a[1]), "r"(a[2]), "r"(a[3]), "r"(b[0]), "r"(b[1]));
}

// ---------------------------------------------------------------------------
// Batched BF16x3 GEMM: C = scale * A·B^T (+bias), fp32-grade (~1e-5) accuracy.
// A row-major [M][K]. BNT=true: B is [n][k]. BNT=false: B is [k][n].
// 256 threads; warps 2(m)x4(n); warp tile 64x(BN/4); mma m16n8k16.
// smem holds bf16x2 k-pairs: row stride SA2=12 words (8 used) -> conflict-free.
// ---------------------------------------------------------------------------
template<int BM, int BN, bool BNT>
__global__ __launch_bounds__(256) void mma_gemm_bf16(
    const float* __restrict__ Ag, int lda, long long Ab, long long Ah,
    const float* __restrict__ Bg, int ldb, long long Bb, long long Bh,
    float* __restrict__ Cg, int ldc, long long Cb, long long Ch,
    const float* __restrict__ bias, int M, int Nn, int K, float scale)
{
    constexpr int SA2 = 12;
    constexpr int SB2 = 12;
    constexpr int WTM = BM / 2, WTN = BN / 4;
    constexpr int MT  = WTM / 16, NT = WTN / 8;
    constexpr int NAL = BM / 64;                 // float4-groups/thread (A tile BMx16)
    constexpr int NBL = BN / 64;                 // (B tile 16xBN or BNx16)

    __shared__ uint32_t AsH[BM * SA2], AsL[BM * SA2];
    __shared__ uint32_t BsH[BN * SB2], BsL[BN * SB2];

    int z  = blockIdx.z;
    int zb = z / H_, zh = z - zb * H_;
    const float* A  = Ag + zb * Ab + zh * Ah;
    const float* Bp = Bg + zb * Bb + zh * Bh;
    float*       C  = Cg + zb * Cb + zh * Ch;

    int t = threadIdx.x, lane = t & 31, warp = t >> 5;
    int wm = warp & 1, wn = warp >> 1;
    int m0 = blockIdx.y * BM, n0 = blockIdx.x * BN;

    float acc[MT][NT][4];
#pragma unroll
    for (int mt = 0; mt < MT; mt++)
#pragma unroll
        for (int nt = 0; nt < NT; nt++)
#pragma unroll
            for (int i = 0; i < 4; i++) acc[mt][nt][i] = 0.f;

    for (int k0 = 0; k0 < K; k0 += 16) {
        // ---- A tile [BM][16] -> packed pairs
#pragma unroll
        for (int i = 0; i < NAL; i++) {
            int f = t + i * 256;
            int row = f >> 2;
            int kq = (f & 3) * 4;
            bool rok = (m0 + row < M);
            float v[4];
#pragma unroll
            for (int j = 0; j < 4; j++) {
                int kk = k0 + kq + j;
                v[j] = (rok && kk < K) ? A[(size_t)(m0 + row) * lda + kk] : 0.f;
            }
            uint32_t h0, l0, h1, l1;
            bsplit2(v[0], v[1], h0, l0);
            bsplit2(v[2], v[3], h1, l1);
            int p = row * SA2 + (kq >> 1);
            AsH[p] = h0; AsH[p + 1] = h1;
            AsL[p] = l0; AsL[p + 1] = l1;
        }
        // ---- B tile -> packed pairs, layout [n][k2]
        if (BNT) {
#pragma unroll
            for (int i = 0; i < NBL; i++) {
                int f = t + i * 256;
                int n = f >> 2;
                int kq = (f & 3) * 4;
                bool nok = (n0 + n < Nn);
                float v[4];
#pragma unroll
                for (int j = 0; j < 4; j++) {
                    int kk = k0 + kq + j;
                    v[j] = (nok && kk < K) ? Bp[(size_t)(n0 + n) * ldb + kk] : 0.f;
                }
                uint32_t h0, l0, h1, l1;
                bsplit2(v[0], v[1], h0, l0);
                bsplit2(v[2], v[3], h1, l1);
                int p = n * SB2 + (kq >> 1);
                BsH[p] = h0; BsH[p + 1] = h1;
                BsL[p] = l0; BsL[p + 1] = l1;
            }
        } else {
            __nv_bfloat16* BH16 = (__nv_bfloat16*)BsH;
            __nv_bfloat16* BL16 = (__nv_bfloat16*)BsL;
#pragma unroll
            for (int i = 0; i < NBL; i++) {
                int f = t + i * 256;
                int kr = f / (BN / 4);
                int n4 = (f % (BN / 4)) * 4;
                bool kok = (k0 + kr < K);
#pragma unroll
                for (int j = 0; j < 4; j++) {
                    int n = n4 + j;
                    float v = (kok && n0 + n < Nn) ? Bp[(size_t)(k0 + kr) * ldb + n0 + n] : 0.f;
                    __nv_bfloat16 h = __float2bfloat16_rn(v);
                    float r = v - __bfloat162float(h);
                    BH16[n * (SB2 * 2) + kr] = h;
                    BL16[n * (SB2 * 2) + kr] = __float2bfloat16_rn(r);
                }
            }
        }
        __syncthreads();

        uint32_t aH[MT][4], aL[MT][4], bH[NT][2], bL[NT][2];
        int k2 = lane & 3;
#pragma unroll
        for (int mt = 0; mt < MT; mt++) {
            int r = wm * WTM + mt * 16 + (lane >> 2);
            aH[mt][0] = AsH[r * SA2 + k2];       aH[mt][1] = AsH[(r + 8) * SA2 + k2];
            aH[mt][2] = AsH[r * SA2 + k2 + 4];   aH[mt][3] = AsH[(r + 8) * SA2 + k2 + 4];
            aL[mt][0] = AsL[r * SA2 + k2];       aL[mt][1] = AsL[(r + 8) * SA2 + k2];
            aL[mt][2] = AsL[r * SA2 + k2 + 4];   aL[mt][3] = AsL[(r + 8) * SA2 + k2 + 4];
        }
#pragma unroll
        for (int nt = 0; nt < NT; nt++) {
            int cN = wn * WTN + nt * 8 + (lane >> 2);
            bH[nt][0] = BsH[cN * SB2 + k2];      bH[nt][1] = BsH[cN * SB2 + k2 + 4];
            bL[nt][0] = BsL[cN * SB2 + k2];      bL[nt][1] = BsL[cN * SB2 + k2 + 4];
        }
#pragma unroll
        for (int mt = 0; mt < MT; mt++)
#pragma unroll
            for (int nt = 0; nt < NT; nt++) {
                mma16(acc[mt][nt], aL[mt], bH[nt]);
                mma16(acc[mt][nt], aH[mt], bL[nt]);
                mma16(acc[mt][nt], aH[mt], bH[nt]);
            }
        __syncthreads();
    }

    // ---- epilogue
#pragma unroll
    for (int mt = 0; mt < MT; mt++) {
        int r0 = m0 + wm * WTM + mt * 16 + (lane >> 2);
#pragma unroll
        for (int nt = 0; nt < NT; nt++) {
            int cN = n0 + wn * WTN + nt * 8 + 2 * (lane & 3);
            float b0 = (bias && cN < Nn)     ? bias[cN]     : 0.f;
            float b1 = (bias && cN + 1 < Nn) ? bias[cN + 1] : 0.f;
            if (r0 < M) {
                if (cN < Nn)     C[(size_t)r0 * ldc + cN]     = acc[mt][nt][0] * scale + b0;
                if (cN + 1 < Nn) C[(size_t)r0 * ldc + cN + 1] = acc[mt][nt][1] * scale + b1;
            }
            if (r0 + 8 < M) {
                if (cN < Nn)     C[(size_t)(r0 + 8) * ldc + cN]     = acc[mt][nt][2] * scale + b0;
                if (cN + 1 < Nn) C[(size_t)(r0 + 8) * ldc + cN + 1] = acc[mt][nt][3] * scale + b1;
            }
        }
    }
}

// ---------------------------------------------------------------------------
// EXACT SGEMM NT (cls path, K-projection only): ascending-k chain. Bit-frozen.
// ---------------------------------------------------------------------------
__global__ __launch_bounds__(256) void sgemm128_nt(
    const float* __restrict__ A, const float* __restrict__ Bw,
    float* __restrict__ Cm, int M, int Nc, int K, int ldc)
{
    __shared__ float As[8][128];
    __shared__ float Bs[8][128];
    int t = threadIdx.x;
    int m0 = blockIdx.y * 128;
    int n0 = blockIdx.x * 128;

    int aRow = t >> 1;
    int aK   = (t & 1) * 4;

    int ty = t >> 4, tx = t & 15;
    int rowBase = ty * 8, colBase = tx * 8;

    float acc[8][8];
#pragma unroll
    for (int i = 0; i < 8; i++)
#pragma unroll
        for (int j = 0; j < 8; j++) acc[i][j] = 0.f;

    const float* aPtr = A + (size_t)(m0 + aRow) * K + aK;
    const float* bPtr = Bw + (size_t)(n0 + aRow) * K + aK;
    bool aOk = (m0 + aRow) < M;
    bool bOk = (n0 + aRow) < Nc;

    for (int k0 = 0; k0 < K; k0 += 8) {
        float4 av = aOk ? *(const float4*)(aPtr + k0)
                        : make_float4(0.f, 0.f, 0.f, 0.f);
        float4 bv = bOk ? *(const float4*)(bPtr + k0)
                        : make_float4(0.f, 0.f, 0.f, 0.f);
        As[aK + 0][aRow] = av.x; As[aK + 1][aRow] = av.y;
        As[aK + 2][aRow] = av.z; As[aK + 3][aRow] = av.w;
        Bs[aK + 0][aRow] = bv.x; Bs[aK + 1][aRow] = bv.y;
        Bs[aK + 2][aRow] = bv.z; Bs[aK + 3][aRow] = bv.w;
        __syncthreads();

#pragma unroll
        for (int k = 0; k < 8; k++) {
            float a[8], b[8];
            *(float4*)(a)     = *(float4*)&As[k][rowBase];
            *(float4*)(a + 4) = *(float4*)&As[k][rowBase + 4];
            *(float4*)(b)     = *(float4*)&Bs[k][colBase];
            *(float4*)(b + 4) = *(float4*)&Bs[k][colBase + 4];
#pragma unroll
            for (int i = 0; i < 8; i++)
#pragma unroll
                for (int j = 0; j < 8; j++)
                    acc[i][j] += a[i] * b[j];
        }
        __syncthreads();
    }

#pragma unroll
    for (int i = 0; i < 8; i++) {
        int m = m0 + rowBase + i;
        if (m >= M) continue;
        float* cp = Cm + (size_t)m * ldc + n0 + colBase;
        float4 c0, c1;
        c0.x = acc[i][0]; c0.y = acc[i][1]; c0.z = acc[i][2]; c0.w = acc[i][3];
        c1.x = acc[i][4]; c1.y = acc[i][5]; c1.z = acc[i][6]; c1.w = acc[i][7];
        *(float4*)(cp)     = c0;
        *(float4*)(cp + 4) = c1;
    }
}

// ---------------------------------------------------------------------------
// EXACT q row 0: grid (B_, 3) x 256, one column per thread, x row in smem.
// Same ascending-k fmaf chain as before (bit-identical values).
// ---------------------------------------------------------------------------
__global__ __launch_bounds__(256) void q0_exact(
    const float* __restrict__ x, const float* __restrict__ Wqkv)
{
    int b = blockIdx.x;
    int c = blockIdx.y * 256 + threadIdx.x;
    __shared__ float xs[C_];
    for (int i = threadIdx.x; i < C_; i += 256)
        xs[i] = x[(size_t)b * N_ * C_ + i];
    __syncthreads();
    const float* w = Wqkv + (size_t)c * C_;
    float acc = 0.f;
#pragma unroll 8
    for (int k = 0; k < C_; k++) acc = fmaf(xs[k], w[k], acc);
    g_q0[b * C_ + c] = acc;
}

// ---------------------------------------------------------------------------
// EXACT row-0 scores: s[b,h,j] = 0.125 * sum_d q0_d * k_jd  (ascending d).
// ---------------------------------------------------------------------------
__global__ void cls_scores()
{
    int z = blockIdx.x;
    int b = z / H_, h = z - b * H_;
    __shared__ float q0s[HD_];
    if (threadIdx.x < HD_) q0s[threadIdx.x] = g_q0[b * C_ + h * HD_ + threadIdx.x];
    __syncthreads();
    for (int j = threadIdx.x; j < N_; j += blockDim.x) {
        const float* kr = g_qkv + (size_t)(b * N_ + j) * QKVC + C_ + h * HD_;
        float acc = 0.f;
#pragma unroll
        for (int d = 0; d < HD_; d++) acc = fmaf(q0s[d], kr[d], acc);
        g_clsS[z * N_ + j] = acc * SCALE_;
    }
}

// ---------------------------------------------------------------------------
// REF-MATCHED cls-row softmax (bit-frozen; source = g_clsS).
// ---------------------------------------------------------------------------
__global__ __launch_bounds__(256) void cls_row_ref()
{
    int z = blockIdx.x;
    const float* __restrict__ S = g_clsS + (size_t)z * N_;
    float* __restrict__ P = g_ph + (size_t)z * N_;

    int t = threadIdx.x;
    int lane = t & 31, wid = t >> 5;
    __shared__ float red[8];
    __shared__ float se[N_];
    __shared__ float zsh;

    float s[4];
    float mx = -INFINITY;
#pragma unroll
    for (int i = 0; i < 4; i++) {
        int j = t + i * 256;
        s[i] = (j < N_) ? S[j] : -INFINITY;
        mx = fmaxf(mx, s[i]);
    }
#pragma unroll
    for (int w = 16; w > 0; w >>= 1)
        mx = fmaxf(mx, __shfl_xor_sync(0xffffffffu, mx, w));
    if (lane == 0) red[wid] = mx;
    __syncthreads();
    mx = red[0];
#pragma unroll
    for (int w = 1; w < 8; w++) mx = fmaxf(mx, red[w]);

#pragma unroll
    for (int i = 0; i < 4; i++) {
        int j = t + i * 256;
        if (j < N_) se[j] = cephes_expf(s[i] - mx);
    }
    __syncthreads();

    if (t == 0) {
        float Z = 0.f;
        for (int j = 0; j < N_; j++) Z += se[j];   // canonical ascending order
        zsh = Z;
    }
    __syncthreads();
    float Z = zsh;

#pragma unroll
    for (int i = 0; i < 4; i++) {
        int j = t + i * 256;
        if (j < N_) P[j] = se[j] / Z;   // IEEE division
    }
}

// ---------------------------------------------------------------------------
// Row softmax over 785 elems (in place); fast path, feeds PV/out only.
// ---------------------------------------------------------------------------
__global__ __launch_bounds__(256) void softmax_rows()
{
    float* __restrict__ p = g_attn + (size_t)blockIdx.x * N_;
    int t = threadIdx.x;
    int lane = t & 31, wid = t >> 5;
    __shared__ float red[8];

    float v[4];
    float mx = -INFINITY;
#pragma unroll
    for (int i = 0; i < 4; i++) {
        int j = t + i * 256;
        v[i] = (j < N_) ? p[j] : -INFINITY;
        mx = fmaxf(mx, v[i]);
    }
#pragma unroll
    for (int s = 16; s > 0; s >>= 1)
        mx = fmaxf(mx, __shfl_xor_sync(0xffffffffu, mx, s));
    if (lane == 0) red[wid] = mx;
    __syncthreads();
    mx = red[0];
#pragma unroll
    for (int w = 1; w < 8; w++) mx = fmaxf(mx, red[w]);

    float sum = 0.f;
#pragma unroll
    for (int i = 0; i < 4; i++) {
        int j = t + i * 256;
        if (j < N_) { v[i] = __expf(v[i] - mx); sum += v[i]; }
    }
#pragma unroll
    for (int s = 16; s > 0; s >>= 1)
        sum += __shfl_xor_sync(0xffffffffu, sum, s);
    __syncthreads();
    if (lane == 0) red[wid] = sum;
    __syncthreads();
    sum = 0.f;
#pragma unroll
    for (int w = 0; w < 8; w++) sum += red[w];

    float inv = 1.f / sum;
#pragma unroll
    for (int i = 0; i < 4; i++) {
        int j = t + i * 256;
        if (j < N_) p[j] = v[i] * inv;
    }
}

// ---------------------------------------------------------------------------
// cls_attn mean over heads (bit-frozen)
// ---------------------------------------------------------------------------
__global__ void cls_mean(float* __restrict__ out_f)
{
    int b = blockIdx.x;
    for (int j = 1 + threadIdx.x; j < N_; j += blockDim.x) {
        float s = 0.f;
#pragma unroll
        for (int h = 0; h < H_; h++)
            s += g_ph[(size_t)(b * H_ + h) * N_ + j];
        float v = s / 12.0f;
        g_cls[b * NM1 + (j - 1)] = v;
        out_f[OFF_CLS + b * NM1 + (j - 1)] = v;
    }
}

// ---------------------------------------------------------------------------
// top-549 by rank counting (ties -> lower index)
// ---------------------------------------------------------------------------
__global__ void topk_sel(float* __restrict__ out_f)
{
    int b = blockIdx.x;
    __shared__ float sv[NM1];
    for (int j = threadIdx.x; j < NM1; j += blockDim.x)
        sv[j] = g_cls[b * NM1 + j];
    __syncthreads();
    for (int j = threadIdx.x; j < NM1; j += blockDim.x) {
        float v = sv[j];
        int rank = 0;
        for (int i = 0; i < NM1; i++) {
            float w = sv[i];
            rank += (w > v) || (w == v && i < j);
        }
        if (rank < LEFT) {
            g_idx[b * LEFT + rank] = j;
            out_f[OFF_IDX + b * LEFT + rank] = (float)j;
        }
    }
}

__global__ void bcast_index(float* __restrict__ out_f)
{
    int total = B_ * LEFT * C_;
    for (int i = blockIdx.x * blockDim.x + threadIdx.x; i < total;
         i += gridDim.x * blockDim.x) {
        int b = i / (LEFT * C_);
        int r = (i / C_) % LEFT;
        out_f[OFF_INDEX + i] = (float)g_idx[b * LEFT + r];
    }
}

// ---------------------------------------------------------------------------
extern "C" void kernel_launch(void* const* d_in, const int* in_sizes, int n_in,
                              void* d_out, int out_size)
{
    const float* x     = (const float*)d_in[0];
    const float* Wqkv  = (const float*)d_in[1];
    const float* Wproj = (const float*)d_in[2];
    const float* bproj = (const float*)d_in[3];
    float* out_f = (float*)d_out;

    float *p_qkv, *p_attn, *p_attnout;
    cudaGetSymbolAddress((void**)&p_qkv, g_qkv);
    cudaGetSymbolAddress((void**)&p_attn, g_attn);
    cudaGetSymbolAddress((void**)&p_attnout, g_attnout);

    // 1. EXACT K-projection (cls path), bit-frozen chain
    sgemm128_nt<<<dim3(6, 99), 256>>>(
        x, Wqkv + 768 * 768, p_qkv + 768, M_, 768, 768, QKVC);

    // 2. BF16x3 Q-projection
    mma_gemm_bf16<128, 128, true><<<dim3(6, 99, 1), 256>>>(
        x, C_, 0, 0, Wqkv, C_, 0, 0, p_qkv, QKVC, 0, 0,
        nullptr, M_, C_, C_, 1.f);

    // 3. BF16x3 V-projection
    mma_gemm_bf16<128, 128, true><<<dim3(6, 99, 1), 256>>>(
        x, C_, 0, 0, Wqkv + 1536 * 768, C_, 0, 0, p_qkv + 1536, QKVC, 0, 0,
        nullptr, M_, C_, C_, 1.f);

    // 4. EXACT q row 0 + row-0 scores (cls path)
    q0_exact<<<dim3(B_, 3), 256>>>(x, Wqkv);
    cls_scores<<<B_ * H_, 256>>>();

    // 5. BF16x3 scores: S = 0.125 * Q K^T  (batched over b,h)
    mma_gemm_bf16<128, 128, true><<<dim3(7, 7, B_ * H_), 256>>>(
        p_qkv, QKVC, (long long)N_ * QKVC, HD_,
        p_qkv + C_, QKVC, (long long)N_ * QKVC, HD_,
        p_attn, N_, (long long)H_ * N_ * N_, (long long)N_ * N_,
        nullptr, N_, N_, HD_, SCALE_);

    // 6. cls softmax (bit-frozen) — reads g_clsS
    cls_row_ref<<<B_ * H_, 256>>>();

    // 7. softmax rows (feeds PV)
    softmax_rows<<<B_ * H_ * N_, 256>>>();

    // 8. BF16x3 PV: O = P V  (NN GEMM, batched)
    mma_gemm_bf16<128, 64, false><<<dim3(1, 7, B_ * H_), 256>>>(
        p_attn, N_, (long long)H_ * N_ * N_, (long long)N_ * N_,
        p_qkv + 2 * C_, QKVC, (long long)N_ * QKVC, HD_,
        p_attnout, C_, (long long)N_ * C_, HD_,
        nullptr, N_, HD_, N_, 1.f);

    // 9. BF16x3 out-projection + bias
    mma_gemm_bf16<128, 128, true><<<dim3(6, 99, 1), 256>>>(
        p_attnout, C_, 0, 0, Wproj, C_, 0, 0, out_f + OFF_OUT, C_, 0, 0,
        bproj, M_, C_, C_, 1.f);

    // 10. cls mean / topk / index broadcast (bit-frozen)
    cls_mean<<<B_, 256>>>(out_f);
    topk_sel<<<B_, 256>>>(out_f);
    bcast_index<<<512, 256>>>(out_f);
}

// round 16
// speedup vs baseline: 1.8129x; 1.1513x over previous
#include <cuda_runtime.h>
#include <cuda_bf16.h>
#include <math.h>
#include <stdint.h>

#define B_    16
#define N_    785
#define C_    768
#define H_    12
#define HD_   64
#define M_    (B_*N_)        // 12560
#define QKVC  (3*C_)         // 2304
#define LEFT  549
#define NM1   784
#define SCALE_ 0.125f
#define PLD   800            // padded P row (25 k-tiles of 32)

// output segment offsets (floats): [out | idx | index | cls_attn]
#define OFF_OUT   0
#define OFF_IDX   9646080
#define OFF_INDEX 9654864
#define OFF_CLS   16400976

// ---------------- scratch (static device allocations) ----------------------
__device__ float g_attn[(size_t)B_ * H_ * N_ * N_];   // fp32 scores
__device__ float g_kexact[M_ * C_];                   // exact K-projection (cls)
__device__ float g_q0[B_ * C_];
__device__ float g_clsS[B_ * H_ * N_];
__device__ float g_ph[B_ * H_ * N_];
__device__ float g_cls[B_ * NM1];
__device__ int   g_idx[B_ * LEFT];

// pre-split bf16 hi/lo operand buffers
__device__ __nv_bfloat16 g_xh[M_ * C_],  g_xl[M_ * C_];
__device__ __nv_bfloat16 g_wqh[C_ * C_], g_wql[C_ * C_];
__device__ __nv_bfloat16 g_wvh[C_ * C_], g_wvl[C_ * C_];
__device__ __nv_bfloat16 g_wph[C_ * C_], g_wpl[C_ * C_];
__device__ __nv_bfloat16 g_qh[M_ * C_],  g_ql[M_ * C_];
__device__ __nv_bfloat16 g_kh[M_ * C_],  g_kl[M_ * C_];
__device__ __nv_bfloat16 g_vh[M_ * C_],  g_vl[M_ * C_];
__device__ __nv_bfloat16 g_phh[(size_t)B_ * H_ * N_ * PLD];
__device__ __nv_bfloat16 g_pll[(size_t)B_ * H_ * N_ * PLD];
__device__ __nv_bfloat16 g_aoh[M_ * C_], g_aol[M_ * C_];

// ---------------------------------------------------------------------------
// Cephes-style expf (bit-matches reference exp). DO NOT TOUCH — cls path.
// ---------------------------------------------------------------------------
__device__ __forceinline__ float cephes_expf(float x)
{
    x = fminf(x, 88.723164f);
    x = fmaxf(x, -87.33654f);
    float m = floorf(fmaf(x, 1.44269504088896341f, 0.5f));
    float r = fmaf(m, -0.693359375f, x);
    r = fmaf(m, 2.12194440e-4f, r);
    float r2 = r * r;
    float y = 1.9875691500E-4f;
    y = fmaf(y, r, 1.3981999507E-3f);
    y = fmaf(y, r, 8.3334519073E-3f);
    y = fmaf(y, r, 4.1665795894E-2f);
    y = fmaf(y, r, 1.6666665459E-1f);
    y = fmaf(y, r, 5.0000001201E-1f);
    y = fmaf(y, r2, r);
    y = y + 1.0f;
    int mi = (int)m;
    float s = __int_as_float((mi + 127) << 23);
    return y * s;
}

__device__ __forceinline__ uint32_t pack2(__nv_bfloat16 a, __nv_bfloat16 b)
{
    return ((uint32_t)__bfloat16_as_ushort(b) << 16) | (uint32_t)__bfloat16_as_ushort(a);
}

__device__ __forceinline__ void mma16(float* c, const uint32_t* a, const uint32_t* b)
{
    asm volatile(
        "mma.sync.aligned.m16n8k16.row.col.f32.bf16.bf16.f32 "
        "{%0,%1,%2,%3}, {%4,%5,%6,%7}, {%8,%9}, {%0,%1,%2,%3};"
        : "+f"(c[0]), "+f"(c[1]), "+f"(c[2]), "+f"(c[3])
        : "r"(a[0]), "r"(a[1]), "r"(a[2]), "r"(a[3]), "r"(b[0]), "r"(b[1]));
}

// ---------------------------------------------------------------------------
// Pre-split bf16x3 GEMM body. A [M][lda] hi/lo bf16. BNT: B[n][k] else B[k][n].
// BK=32. Accumulation: ascending k16 steps, passes (aL*bH, aH*bL, aH*bH) —
// identical order to round-14 kernel (bit-compatible results).
// ---------------------------------------------------------------------------
template<int BM, int BN, bool BNT>
__device__ __forceinline__ void gemm_body(
    char* sraw,
    const __nv_bfloat16* __restrict__ AH, const __nv_bfloat16* __restrict__ AL, int lda,
    const __nv_bfloat16* __restrict__ BH, const __nv_bfloat16* __restrict__ BL, int ldb,
    float* C, int ldc,
    __nv_bfloat16* OH, __nv_bfloat16* OL, int ldo,
    const float* bias, int M, int Nn, int K, int KT, float scale,
    int bm, int bn)
{
    constexpr int SAW = 20;                 // words per row (16 used + 4 pad)
    constexpr int ASZ = BM * SAW, BSZ = BN * SAW;
    uint32_t* AsH = (uint32_t*)sraw;
    uint32_t* AsL = AsH + ASZ;
    uint32_t* BsH = AsL + ASZ;
    uint32_t* BsL = BsH + BSZ;

    const int t = threadIdx.x, lane = t & 31, warp = t >> 5;
    const int wm = warp & 1, wn = warp >> 1;
    const int m0 = bm * BM, n0 = bn * BN;
    constexpr int WTM = BM / 2, WTN = BN / 4;
    constexpr int MT = WTM / 16, NT = WTN / 8;

    float acc[MT][NT][4];
#pragma unroll
    for (int mt = 0; mt < MT; mt++)
#pragma unroll
        for (int nt = 0; nt < NT; nt++)
#pragma unroll
            for (int i = 0; i < 4; i++) acc[mt][nt][i] = 0.f;

    for (int kt = 0; kt < KT; kt++) {
        int k0 = kt * 32;
        // ---- A tile [BM][32] via uint4 (8 bf16)
        constexpr int NA = (BM * 4) / 256;
#pragma unroll
        for (int i = 0; i < NA; i++) {
            int f = t + i * 256, row = f >> 2, w4 = f & 3;
            uint4 vh = make_uint4(0, 0, 0, 0), vl = vh;
            if (m0 + row < M) {
                size_t off = (size_t)(m0 + row) * lda + k0 + w4 * 8;
                vh = *(const uint4*)(AH + off);
                vl = *(const uint4*)(AL + off);
            }
            *(uint4*)&AsH[row * SAW + w4 * 4] = vh;
            *(uint4*)&AsL[row * SAW + w4 * 4] = vl;
        }
        // ---- B tile
        if (BNT) {
            constexpr int NB = (BN * 4) / 256;
#pragma unroll
            for (int i = 0; i < NB; i++) {
                int f = t + i * 256, row = f >> 2, w4 = f & 3;
                uint4 vh = make_uint4(0, 0, 0, 0), vl = vh;
                if (n0 + row < Nn) {
                    size_t off = (size_t)(n0 + row) * ldb + k0 + w4 * 8;
                    vh = *(const uint4*)(BH + off);
                    vl = *(const uint4*)(BL + off);
                }
                *(uint4*)&BsH[row * SAW + w4 * 4] = vh;
                *(uint4*)&BsL[row * SAW + w4 * 4] = vl;
            }
        } else {
            constexpr int NB = BN / 64;
            __nv_bfloat16* BH16 = (__nv_bfloat16*)BsH;
            __nv_bfloat16* BL16 = (__nv_bfloat16*)BsL;
#pragma unroll
            for (int i = 0; i < NB; i++) {
                int f = t + i * 256;
                int kr = f / (BN / 8), n8 = (f % (BN / 8)) * 8;
                uint4 vh = make_uint4(0, 0, 0, 0), vl = vh;
                if (k0 + kr < K) {
                    size_t off = (size_t)(k0 + kr) * ldb + n0 + n8;
                    vh = *(const uint4*)(BH + off);
                    vl = *(const uint4*)(BL + off);
                }
                __nv_bfloat16 th[8], tl[8];
                *(uint4*)th = vh; *(uint4*)tl = vl;
#pragma unroll
                for (int j = 0; j < 8; j++) {
                    BH16[(n8 + j) * (SAW * 2) + kr] = th[j];
                    BL16[(n8 + j) * (SAW * 2) + kr] = tl[j];
                }
            }
        }
        __syncthreads();

#pragma unroll
        for (int k8 = 0; k8 < 16; k8 += 8) {
            uint32_t aH[MT][4], aL[MT][4], bH[NT][2], bL[NT][2];
            int k2 = (lane & 3) + k8;
#pragma unroll
            for (int mt = 0; mt < MT; mt++) {
                int r = wm * WTM + mt * 16 + (lane >> 2);
                aH[mt][0] = AsH[r * SAW + k2];       aH[mt][1] = AsH[(r + 8) * SAW + k2];
                aH[mt][2] = AsH[r * SAW + k2 + 4];   aH[mt][3] = AsH[(r + 8) * SAW + k2 + 4];
                aL[mt][0] = AsL[r * SAW + k2];       aL[mt][1] = AsL[(r + 8) * SAW + k2];
                aL[mt][2] = AsL[r * SAW + k2 + 4];   aL[mt][3] = AsL[(r + 8) * SAW + k2 + 4];
            }
#pragma unroll
            for (int nt = 0; nt < NT; nt++) {
                int cN = wn * WTN + nt * 8 + (lane >> 2);
                bH[nt][0] = BsH[cN * SAW + k2];      bH[nt][1] = BsH[cN * SAW + k2 + 4];
                bL[nt][0] = BsL[cN * SAW + k2];      bL[nt][1] = BsL[cN * SAW + k2 + 4];
            }
#pragma unroll
            for (int mt = 0; mt < MT; mt++)
#pragma unroll
                for (int nt = 0; nt < NT; nt++) {
                    mma16(acc[mt][nt], aL[mt], bH[nt]);
                    mma16(acc[mt][nt], aH[mt], bL[nt]);
                    mma16(acc[mt][nt], aH[mt], bH[nt]);
                }
        }
        __syncthreads();
    }

    // ---- epilogue (fp32 and/or hi/lo split outputs)
#pragma unroll
    for (int mt = 0; mt < MT; mt++) {
        int r0 = m0 + wm * WTM + mt * 16 + (lane >> 2);
#pragma unroll
        for (int nt = 0; nt < NT; nt++) {
            int cN = n0 + wn * WTN + nt * 8 + 2 * (lane & 3);
            float b0 = 0.f, b1 = 0.f;
            if (bias) {
                b0 = (cN < Nn) ? bias[cN] : 0.f;
                b1 = (cN + 1 < Nn) ? bias[cN + 1] : 0.f;
            }
            float vals[4];
            vals[0] = acc[mt][nt][0] * scale + b0;
            vals[1] = acc[mt][nt][1] * scale + b1;
            vals[2] = acc[mt][nt][2] * scale + b0;
            vals[3] = acc[mt][nt][3] * scale + b1;
#pragma unroll
            for (int rr = 0; rr < 2; rr++) {
                int m = r0 + rr * 8;
                if (m >= M) continue;
#pragma unroll
                for (int cc = 0; cc < 2; cc++) {
                    int n = cN + cc;
                    if (n >= Nn) continue;
                    float v = vals[rr * 2 + cc];
                    if (C) C[(size_t)m * ldc + n] = v;
                    if (OH) {
                        __nv_bfloat16 h = __float2bfloat16_rn(v);
                        OH[(size_t)m * ldo + n] = h;
                        OL[(size_t)m * ldo + n] = __float2bfloat16_rn(v - __bfloat162float(h));
                    }
                }
            }
        }
    }
}

// ---------------------------------------------------------------------------
// Phase 0: split inputs (x, Wq, Wv, Wproj) into bf16 hi/lo.
// ---------------------------------------------------------------------------
__global__ __launch_bounds__(256) void split_inputs(
    const float* __restrict__ x, const float* __restrict__ Wqkv,
    const float* __restrict__ Wproj)
{
    const int NX = M_ * C_;
    const int NW = C_ * C_;
    const int tot4 = (NX + 3 * NW) / 4;
    for (int i4 = blockIdx.x * blockDim.x + threadIdx.x; i4 < tot4;
         i4 += gridDim.x * blockDim.x) {
        int base = i4 * 4;
        const float* src; __nv_bfloat16 *dh, *dl; int off;
        if (base < NX)               { off = base;               src = x;                 dh = g_xh;  dl = g_xl;  }
        else if (base < NX + NW)     { off = base - NX;          src = Wqkv;              dh = g_wqh; dl = g_wql; }
        else if (base < NX + 2 * NW) { off = base - NX - NW;     src = Wqkv + 1536 * C_;  dh = g_wvh; dl = g_wvl; }
        else                         { off = base - NX - 2 * NW; src = Wproj;             dh = g_wph; dl = g_wpl; }
        float4 v = *(const float4*)(src + off);
        __nv_bfloat16 h0 = __float2bfloat16_rn(v.x), h1 = __float2bfloat16_rn(v.y);
        __nv_bfloat16 h2 = __float2bfloat16_rn(v.z), h3 = __float2bfloat16_rn(v.w);
        *(uint2*)(dh + off) = make_uint2(pack2(h0, h1), pack2(h2, h3));
        __nv_bfloat16 l0 = __float2bfloat16_rn(v.x - __bfloat162float(h0));
        __nv_bfloat16 l1 = __float2bfloat16_rn(v.y - __bfloat162float(h1));
        __nv_bfloat16 l2 = __float2bfloat16_rn(v.z - __bfloat162float(h2));
        __nv_bfloat16 l3 = __float2bfloat16_rn(v.w - __bfloat162float(h3));
        *(uint2*)(dl + off) = make_uint2(pack2(l0, l1), pack2(l2, l3));
    }
}

// ---------------------------------------------------------------------------
// Phase 1 (mixed grid (99,6,4)): z=0 exact K SIMT sgemm; z=1 Q bf16; z=2 V bf16;
// z=3 exact q0 chains. Overlaps FMA-bound and tensor-bound blocks.
// ---------------------------------------------------------------------------
__global__ __launch_bounds__(256, 2) void phase1(
    const float* __restrict__ x, const float* __restrict__ Wqkv)
{
    __shared__ char sraw[40960];
    int z = blockIdx.z;
    if (z == 0) {
        // ---- EXACT K-projection (cls path): ascending-k fma chain, bit-frozen
        float (*As)[128] = (float(*)[128])sraw;
        float (*Bs)[128] = (float(*)[128])(sraw + 8 * 128 * 4);
        const float* A  = x;
        const float* Bw = Wqkv + 768 * 768;   // k rows
        const int M = M_, Nc = 768, K = 768;

        int t = threadIdx.x;
        int m0 = blockIdx.x * 128;
        int n0 = blockIdx.y * 128;
        int aRow = t >> 1;
        int aK   = (t & 1) * 4;
        int ty = t >> 4, tx = t & 15;
        int rowBase = ty * 8, colBase = tx * 8;

        float acc[8][8];
#pragma unroll
        for (int i = 0; i < 8; i++)
#pragma unroll
            for (int j = 0; j < 8; j++) acc[i][j] = 0.f;

        const float* aPtr = A + (size_t)(m0 + aRow) * K + aK;
        const float* bPtr = Bw + (size_t)(n0 + aRow) * K + aK;
        bool aOk = (m0 + aRow) < M;
        bool bOk = (n0 + aRow) < Nc;

        for (int k0 = 0; k0 < K; k0 += 8) {
            float4 av = aOk ? *(const float4*)(aPtr + k0)
                            : make_float4(0.f, 0.f, 0.f, 0.f);
            float4 bv = bOk ? *(const float4*)(bPtr + k0)
                            : make_float4(0.f, 0.f, 0.f, 0.f);
            As[aK + 0][aRow] = av.x; As[aK + 1][aRow] = av.y;
            As[aK + 2][aRow] = av.z; As[aK + 3][aRow] = av.w;
            Bs[aK + 0][aRow] = bv.x; Bs[aK + 1][aRow] = bv.y;
            Bs[aK + 2][aRow] = bv.z; Bs[aK + 3][aRow] = bv.w;
            __syncthreads();

#pragma unroll
            for (int k = 0; k < 8; k++) {
                float a[8], b[8];
                *(float4*)(a)     = *(float4*)&As[k][rowBase];
                *(float4*)(a + 4) = *(float4*)&As[k][rowBase + 4];
                *(float4*)(b)     = *(float4*)&Bs[k][colBase];
                *(float4*)(b + 4) = *(float4*)&Bs[k][colBase + 4];
#pragma unroll
                for (int i = 0; i < 8; i++)
#pragma unroll
                    for (int j = 0; j < 8; j++)
                        acc[i][j] += a[i] * b[j];
            }
            __syncthreads();
        }

#pragma unroll
        for (int i = 0; i < 8; i++) {
            int m = m0 + rowBase + i;
            if (m >= M) continue;
            float* cp = g_kexact + (size_t)m * 768 + n0 + colBase;
            float4 c0, c1;
            c0.x = acc[i][0]; c0.y = acc[i][1]; c0.z = acc[i][2]; c0.w = acc[i][3];
            c1.x = acc[i][4]; c1.y = acc[i][5]; c1.z = acc[i][6]; c1.w = acc[i][7];
            *(float4*)(cp)     = c0;
            *(float4*)(cp + 4) = c1;
            // additive hi/lo split (does not change fp32 bits above)
#pragma unroll
            for (int j = 0; j < 8; j++) {
                float v = acc[i][j];
                __nv_bfloat16 h = __float2bfloat16_rn(v);
                size_t o = (size_t)m * 768 + n0 + colBase + j;
                g_kh[o] = h;
                g_kl[o] = __float2bfloat16_rn(v - __bfloat162float(h));
            }
        }
    } else if (z == 1) {
        gemm_body<128, 128, true>(sraw, g_xh, g_xl, C_, g_wqh, g_wql, C_,
            nullptr, 0, g_qh, g_ql, C_, nullptr, M_, C_, C_, 24, 1.f,
            blockIdx.x, blockIdx.y);
    } else if (z == 2) {
        gemm_body<128, 128, true>(sraw, g_xh, g_xl, C_, g_wvh, g_wvl, C_,
            nullptr, 0, g_vh, g_vl, C_, nullptr, M_, C_, C_, 24, 1.f,
            blockIdx.x, blockIdx.y);
    } else {
        // ---- EXACT q row 0 (cls path): same ascending-k fmaf chain
        int bid = blockIdx.y * 99 + blockIdx.x;
        if (bid >= 48) return;
        int b = bid / 3;
        int c = (bid % 3) * 256 + threadIdx.x;
        float* xs = (float*)sraw;
        for (int i = threadIdx.x; i < C_; i += 256)
            xs[i] = x[(size_t)b * N_ * C_ + i];
        __syncthreads();
        const float* w = Wqkv + (size_t)c * C_;
        float acc = 0.f;
#pragma unroll 8
        for (int k = 0; k < C_; k++) acc = fmaf(xs[k], w[k], acc);
        g_q0[b * C_ + c] = acc;
    }
}

// ---------------------------------------------------------------------------
// Phase 2 (mixed grid (7,7,196)): z<192 scores bf16x3; z>=192 exact cls_scores.
// ---------------------------------------------------------------------------
__global__ __launch_bounds__(256, 2) void phase2()
{
    __shared__ char sraw[40960];
    int z = blockIdx.z;
    if (z < 192) {
        int zb = z / H_, zh = z - zb * H_;
        const __nv_bfloat16* AH = g_qh + (size_t)zb * N_ * C_ + zh * HD_;
        const __nv_bfloat16* AL = g_ql + (size_t)zb * N_ * C_ + zh * HD_;
        const __nv_bfloat16* BH = g_kh + (size_t)zb * N_ * C_ + zh * HD_;
        const __nv_bfloat16* BL = g_kl + (size_t)zb * N_ * C_ + zh * HD_;
        float* C = g_attn + (size_t)z * N_ * N_;
        gemm_body<128, 128, true>(sraw, AH, AL, C_, BH, BL, C_,
            C, N_, nullptr, nullptr, 0, nullptr, N_, N_, 64, 2, SCALE_,
            blockIdx.y, blockIdx.x);
    } else {
        int cid = (z - 192) * 49 + blockIdx.y * 7 + blockIdx.x;
        if (cid >= 192) return;
        // ---- EXACT row-0 scores (cls path, bit-frozen)
        int b = cid / H_, h = cid - b * H_;
        __shared__ float q0s[HD_];
        if (threadIdx.x < HD_) q0s[threadIdx.x] = g_q0[b * C_ + h * HD_ + threadIdx.x];
        __syncthreads();
        for (int j = threadIdx.x; j < N_; j += blockDim.x) {
            const float* kr = g_kexact + (size_t)(b * N_ + j) * C_ + h * HD_;
            float acc = 0.f;
#pragma unroll
            for (int d = 0; d < HD_; d++) acc = fmaf(q0s[d], kr[d], acc);
            g_clsS[cid * N_ + j] = acc * SCALE_;
        }
    }
}

// ---------------------------------------------------------------------------
// Phase 3 (mixed 1D grid): softmax rows (write split P) + cls_row_ref.
// ---------------------------------------------------------------------------
__global__ __launch_bounds__(256) void phase3()
{
    __shared__ float red[8];
    __shared__ float se[N_];
    __shared__ float zsh;

    int bid = blockIdx.x;
    int t = threadIdx.x;
    int lane = t & 31, wid = t >> 5;

    if (bid < B_ * H_ * N_) {
        // ---- softmax over one score row; emit bf16 hi/lo P (PLD-padded)
        const float* __restrict__ p = g_attn + (size_t)bid * N_;
        float v[4];
        float mx = -INFINITY;
#pragma unroll
        for (int i = 0; i < 4; i++) {
            int j = t + i * 256;
            v[i] = (j < N_) ? p[j] : -INFINITY;
            mx = fmaxf(mx, v[i]);
        }
#pragma unroll
        for (int s = 16; s > 0; s >>= 1)
            mx = fmaxf(mx, __shfl_xor_sync(0xffffffffu, mx, s));
        if (lane == 0) red[wid] = mx;
        __syncthreads();
        mx = red[0];
#pragma unroll
        for (int w = 1; w < 8; w++) mx = fmaxf(mx, red[w]);

        float sum = 0.f;
#pragma unroll
        for (int i = 0; i < 4; i++) {
            int j = t + i * 256;
            if (j < N_) { v[i] = __expf(v[i] - mx); sum += v[i]; }
        }
#pragma unroll
        for (int s = 16; s > 0; s >>= 1)
            sum += __shfl_xor_sync(0xffffffffu, sum, s);
        __syncthreads();
        if (lane == 0) red[wid] = sum;
        __syncthreads();
        sum = 0.f;
#pragma unroll
        for (int w = 0; w < 8; w++) sum += red[w];

        float inv = 1.f / sum;
        size_t ro = (size_t)bid * PLD;
        __nv_bfloat16 z16 = __float2bfloat16_rn(0.f);
#pragma unroll
        for (int i = 0; i < 4; i++) {
            int j = t + i * 256;
            if (j < N_) {
                float pv = v[i] * inv;
                __nv_bfloat16 h = __float2bfloat16_rn(pv);
                g_phh[ro + j] = h;
                g_pll[ro + j] = __float2bfloat16_rn(pv - __bfloat162float(h));
            } else if (j < PLD) {
                g_phh[ro + j] = z16;
                g_pll[ro + j] = z16;
            }
        }
    } else {
        // ---- REF-MATCHED cls-row softmax (bit-frozen)
        int z = bid - B_ * H_ * N_;
        const float* __restrict__ S = g_clsS + (size_t)z * N_;
        float* __restrict__ P = g_ph + (size_t)z * N_;

        float s[4];
        float mx = -INFINITY;
#pragma unroll
        for (int i = 0; i < 4; i++) {
            int j = t + i * 256;
            s[i] = (j < N_) ? S[j] : -INFINITY;
            mx = fmaxf(mx, s[i]);
        }
#pragma unroll
        for (int w = 16; w > 0; w >>= 1)
            mx = fmaxf(mx, __shfl_xor_sync(0xffffffffu, mx, w));
        if (lane == 0) red[wid] = mx;
        __syncthreads();
        mx = red[0];
#pragma unroll
        for (int w = 1; w < 8; w++) mx = fmaxf(mx, red[w]);

#pragma unroll
        for (int i = 0; i < 4; i++) {
            int j = t + i * 256;
            if (j < N_) se[j] = cephes_expf(s[i] - mx);
        }
        __syncthreads();

        if (t == 0) {
            float Z = 0.f;
            for (int j = 0; j < N_; j++) Z += se[j];
            zsh = Z;
        }
        __syncthreads();
        float Z = zsh;

#pragma unroll
        for (int i = 0; i < 4; i++) {
            int j = t + i * 256;
            if (j < N_) P[j] = se[j] / Z;
        }
    }
}

// ---------------------------------------------------------------------------
// PV: O = P V (NN, batched); inputs pre-split; outputs split attnout.
// ---------------------------------------------------------------------------
__global__ __launch_bounds__(256, 2) void pv_kernel()
{
    __shared__ char sraw[30720];
    int z = blockIdx.z;
    int zb = z / H_, zh = z - zb * H_;
    const __nv_bfloat16* AH = g_phh + (size_t)z * N_ * PLD;
    const __nv_bfloat16* AL = g_pll + (size_t)z * N_ * PLD;
    const __nv_bfloat16* BH = g_vh + (size_t)zb * N_ * C_ + zh * HD_;
    const __nv_bfloat16* BL = g_vl + (size_t)zb * N_ * C_ + zh * HD_;
    __nv_bfloat16* OH = g_aoh + (size_t)zb * N_ * C_ + zh * HD_;
    __nv_bfloat16* OL = g_aol + (size_t)zb * N_ * C_ + zh * HD_;
    gemm_body<128, 64, false>(sraw, AH, AL, PLD, BH, BL, C_,
        nullptr, 0, OH, OL, C_, nullptr, N_, HD_, N_, 25, 1.f,
        blockIdx.y, blockIdx.x);
}

// ---------------------------------------------------------------------------
// out-projection: out = AO Wp^T + b (fp32 out only)
// ---------------------------------------------------------------------------
__global__ __launch_bounds__(256, 2) void outproj_kernel(
    const float* __restrict__ bias, float* __restrict__ out)
{
    __shared__ char sraw[40960];
    gemm_body<128, 128, true>(sraw, g_aoh, g_aol, C_, g_wph, g_wpl, C_,
        out, C_, nullptr, nullptr, 0, bias, M_, C_, C_, 24, 1.f,
        blockIdx.y, blockIdx.x);
}

// ---------------------------------------------------------------------------
// cls_attn mean over heads (bit-frozen)
// ---------------------------------------------------------------------------
__global__ void cls_mean(float* __restrict__ out_f)
{
    int b = blockIdx.x;
    for (int j = 1 + threadIdx.x; j < N_; j += blockDim.x) {
        float s = 0.f;
#pragma unroll
        for (int h = 0; h < H_; h++)
            s += g_ph[(size_t)(b * H_ + h) * N_ + j];
        float v = s / 12.0f;
        g_cls[b * NM1 + (j - 1)] = v;
        out_f[OFF_CLS + b * NM1 + (j - 1)] = v;
    }
}

// ---------------------------------------------------------------------------
// top-549 by rank counting (ties -> lower index) — bit-frozen
// ---------------------------------------------------------------------------
__global__ void topk_sel(float* __restrict__ out_f)
{
    int b = blockIdx.x;
    __shared__ float sv[NM1];
    for (int j = threadIdx.x; j < NM1; j += blockDim.x)
        sv[j] = g_cls[b * NM1 + j];
    __syncthreads();
    for (int j = threadIdx.x; j < NM1; j += blockDim.x) {
        float v = sv[j];
        int rank = 0;
        for (int i = 0; i < NM1; i++) {
            float w = sv[i];
            rank += (w > v) || (w == v && i < j);
        }
        if (rank < LEFT) {
            g_idx[b * LEFT + rank] = j;
            out_f[OFF_IDX + b * LEFT + rank] = (float)j;
        }
    }
}

__global__ void bcast_index(float* __restrict__ out_f)
{
    int total = B_ * LEFT * C_;
    for (int i = blockIdx.x * blockDim.x + threadIdx.x; i < total;
         i += gridDim.x * blockDim.x) {
        int b = i / (LEFT * C_);
        int r = (i / C_) % LEFT;
        out_f[OFF_INDEX + i] = (float)g_idx[b * LEFT + r];
    }
}

// ---------------------------------------------------------------------------
extern "C" void kernel_launch(void* const* d_in, const int* in_sizes, int n_in,
                              void* d_out, int out_size)
{
    const float* x     = (const float*)d_in[0];
    const float* Wqkv  = (const float*)d_in[1];
    const float* Wproj = (const float*)d_in[2];
    const float* bproj = (const float*)d_in[3];
    float* out_f = (float*)d_out;

    // 0. split x / Wq / Wv / Wproj into bf16 hi/lo
    split_inputs<<<4096, 256>>>(x, Wqkv, Wproj);

    // 1. mixed: exact K (SIMT) + Q-proj + V-proj (tensor) + exact q0
    phase1<<<dim3(99, 6, 4), 256>>>(x, Wqkv);

    // 2. mixed: scores bf16x3 + exact cls row-0 scores
    phase2<<<dim3(7, 7, 196), 256>>>();

    // 3. mixed: softmax (emit split P) + bit-frozen cls softmax
    phase3<<<B_ * H_ * N_ + B_ * H_, 256>>>();

    // 4. PV
    pv_kernel<<<dim3(1, 7, 192), 256>>>();

    // 5. cls mean (tiny)
    cls_mean<<<B_, 256>>>(out_f);

    // 6. out-projection
    outproj_kernel<<<dim3(6, 99, 1), 256>>>(bproj, out_f + OFF_OUT);

    // 7. top-k + index broadcast (bit-frozen)
    topk_sel<<<B_, 256>>>(out_f);
    bcast_index<<<512, 256>>>(out_f);
}